// round 6
// baseline (speedup 1.0000x reference)
#include <cuda_runtime.h>
#include <math.h>
#include <stdint.h>

#define MAXN 20000
#define GRID 148
#define BLK  384

// ---------------- scratch (static device memory; no allocs) ----------------
__device__ float4 g_ah_src[MAXN * 34];   // 34 rows/node, row 33 = zero pad
__device__ float4 g_ah_dst[MAXN * 34];
__device__ float  g_as_src[MAXN * 64];
__device__ float  g_as_dst[MAXN * 64];
__device__ float  g_s_acc[MAXN * 64];
__device__ float  g_v_acc[MAXN * 12];
__device__ float  g_cnt[MAXN];
__device__ unsigned g_bar[2];            // ticket barriers (monotonic, replay-safe)

// ---------------- shared-memory weight layout (float indices) ----------------
#define O_WES   0
#define O_WVN   (O_WES + 32*72)
#define O_B1    (O_WVN + 34*72)
#define O_WHE   (O_B1 + 64)
#define O_WV1   (O_WHE + 36)
#define O_WSV1  (O_WV1 + 136)
#define O_BSV1  (O_WSV1 + 256)
#define O_W2H   (O_BSV1 + 4)
#define O_W2S   (O_W2H + 16)
#define O_B2    (O_W2S + 68*72)
#define O_WV2   (O_B2 + 64)
#define O_WSV2  (O_WV2 + 16)
#define O_BSV2  (O_WSV2 + 256)
#define O_W3H   (O_BSV2 + 4)
#define O_W3S   (O_W3H + 16)
#define O_B3    (O_W3S + 68*72)
#define O_WV3   (O_B3 + 64)
#define O_WSV3  (O_WV3 + 16)
#define O_BSV3  (O_WSV3 + 256)
#define O_XS    (O_BSV3 + 4)             // 3 * 128 floats for prep
#define SMEM_FLOATS (O_XS + 384)
#define SMEM_BYTES (SMEM_FLOATS * 4)

typedef unsigned long long ull;

__device__ __forceinline__ float fsig(float x) {
    float t;
    asm("ex2.approx.f32 %0, %1;" : "=f"(t) : "f"(x * -1.4426950408889634f));
    float r;
    asm("rcp.approx.f32 %0, %1;" : "=f"(r) : "f"(t + 1.0f));
    return r;
}
__device__ __forceinline__ float fsqrt_(float x) {
    float r;
    asm("sqrt.approx.f32 %0, %1;" : "=f"(r) : "f"(x));
    return r;
}
__device__ __forceinline__ ull pack2(float lo, float hi) {
    ull r;
    asm("mov.b64 %0, {%1, %2};" : "=l"(r) : "f"(lo), "f"(hi));
    return r;
}
__device__ __forceinline__ void unpack2(float& lo, float& hi, ull a) {
    asm("mov.b64 {%0, %1}, %2;" : "=f"(lo), "=f"(hi) : "l"(a));
}

__device__ __forceinline__ void fma_row32(ull acc[16], float x, const float* row) {
    ull xx = pack2(x, x);
    const ulonglong2* r2 = (const ulonglong2*)row;
#pragma unroll
    for (int j = 0; j < 8; j++) {
        ulonglong2 w = r2[j];
        asm("fma.rn.f32x2 %0, %1, %2, %0;" : "+l"(acc[2*j])   : "l"(xx), "l"(w.x));
        asm("fma.rn.f32x2 %0, %1, %2, %0;" : "+l"(acc[2*j+1]) : "l"(xx), "l"(w.y));
    }
}

// grid-wide barrier: ticket design, counter never resets (graph-replay safe)
__device__ __forceinline__ void grid_barrier(int which, unsigned nblocks) {
    __threadfence();
    __syncthreads();
    if (threadIdx.x == 0) {
        unsigned t = atomicAdd(&g_bar[which], 1u);
        unsigned target = (t / nblocks + 1u) * nblocks;
        unsigned v;
        do {
            asm volatile("ld.acquire.gpu.u32 %0, [%1];" : "=r"(v) : "l"(&g_bar[which]));
        } while ((int)(v - target) < 0);
    }
    __syncthreads();
    __threadfence();
}

// ---------------- GVP layer for layers 2/3 (64 scalars split over lane pair) ----------------
__device__ __forceinline__ void gvp64(
    int p, const float* sm, const float sf_in[32], const float vin[12],
    float sf_out[32], float vout[12],
    int o_wh, int o_ws, int o_b, int o_wv, int o_wsv, int o_bsv, bool final_)
{
    float vh[12];
#pragma unroll
    for (int h = 0; h < 4; h++) {
        float x = 0.f, y = 0.f, z = 0.f;
#pragma unroll
        for (int o = 0; o < 4; o++) {
            float w = sm[o_wh + o * 4 + h];
            x += vin[o*3+0] * w; y += vin[o*3+1] * w; z += vin[o*3+2] * w;
        }
        vh[h*3+0] = x; vh[h*3+1] = y; vh[h*3+2] = z;
    }
    float vn2[4];
#pragma unroll
    for (int h = 0; h < 4; h++)
        vn2[h] = fsqrt_(fmaxf(vh[h*3]*vh[h*3] + vh[h*3+1]*vh[h*3+1] + vh[h*3+2]*vh[h*3+2], 1e-8f));
    float vo2[12];
#pragma unroll
    for (int o = 0; o < 4; o++) {
        float x = 0.f, y = 0.f, z = 0.f;
#pragma unroll
        for (int h = 0; h < 4; h++) {
            float w = sm[o_wv + h * 4 + o];
            x += vh[h*3+0] * w; y += vh[h*3+1] * w; z += vh[h*3+2] * w;
        }
        vo2[o*3+0] = x; vo2[o*3+1] = y; vo2[o*3+2] = z;
    }
    ull acc[16];
    {
        const float4* B = (const float4*)(sm + o_b + 32 * p);
#pragma unroll
        for (int j = 0; j < 8; j++) {
            float4 b = B[j];
            acc[2*j]   = pack2(b.x, b.y);
            acc[2*j+1] = pack2(b.z, b.w);
        }
    }
    const float* W = sm + o_ws;
    int half = 36 * p;
#pragma unroll
    for (int r = 0; r < 32; r++) {
        float mine  = sf_in[r];
        float other = __shfl_xor_sync(0xffffffffu, mine, 1);
        float klo = p ? other : mine;
        float khi = p ? mine  : other;
        fma_row32(acc, klo, W + r * 72 + half);
        fma_row32(acc, khi, W + (32 + r) * 72 + half);
    }
#pragma unroll
    for (int h = 0; h < 4; h++)
        fma_row32(acc, vn2[h], W + (64 + h) * 72 + half);
#pragma unroll
    for (int j = 0; j < 16; j++) unpack2(sf_out[2*j], sf_out[2*j+1], acc[j]);

    float p0 = 0.f, p1 = 0.f, p2 = 0.f, p3 = 0.f;
#pragma unroll
    for (int r = 0; r < 32; r++) {
        float t = final_ ? sf_out[r] : fsig(sf_out[r]);
        float4 w = *(const float4*)(sm + o_wsv + (32 * p + r) * 4);
        p0 += t * w.x; p1 += t * w.y; p2 += t * w.z; p3 += t * w.w;
    }
    float g0 = sm[o_bsv+0] + p0 + __shfl_xor_sync(0xffffffffu, p0, 1);
    float g1 = sm[o_bsv+1] + p1 + __shfl_xor_sync(0xffffffffu, p1, 1);
    float g2 = sm[o_bsv+2] + p2 + __shfl_xor_sync(0xffffffffu, p2, 1);
    float g3 = sm[o_bsv+3] + p3 + __shfl_xor_sync(0xffffffffu, p3, 1);
    g0 = fsig(g0); g1 = fsig(g1); g2 = fsig(g2); g3 = fsig(g3);
#pragma unroll
    for (int c = 0; c < 3; c++) {
        vout[0*3+c] = vo2[0*3+c] * g0;
        vout[1*3+c] = vo2[1*3+c] * g1;
        vout[2*3+c] = vo2[2*3+c] * g2;
        vout[3*3+c] = vo2[3*3+c] * g3;
    }
    if (!final_) {
#pragma unroll
        for (int r = 0; r < 32; r++) sf_out[r] = fmaxf(sf_out[r], 0.f);
    }
}

__device__ __forceinline__ void smcopy(float* d, const float* s, int n) {
    for (int i = threadIdx.x; i < n; i += blockDim.x) d[i] = s[i];
}
__device__ __forceinline__ void smcopy_pad(float* d, const float* s, int K) {
    for (int i = threadIdx.x; i < K * 64; i += blockDim.x) {
        int k = i >> 6, c = i & 63;
        d[k * 72 + c + (c >= 32 ? 4 : 0)] = s[i];
    }
}

// ==================== megakernel ====================
__global__ void __launch_bounds__(BLK, 1) mega_kernel(
    const float* __restrict__ node_s, const float* __restrict__ node_v,
    const int* __restrict__ ei,
    const float* __restrict__ edge_s, const float* __restrict__ edge_v,
    const int* __restrict__ mask,
    const float* __restrict__ w1_wh, const float* __restrict__ w1_ws,
    const float* __restrict__ w1_wsb, const float* __restrict__ w1_wv,
    const float* __restrict__ w1_wsv, const float* __restrict__ w1_wsvb,
    const float* __restrict__ w2_wh, const float* __restrict__ w2_ws,
    const float* __restrict__ w2_wsb, const float* __restrict__ w2_wv,
    const float* __restrict__ w2_wsv, const float* __restrict__ w2_wsvb,
    const float* __restrict__ w3_wh, const float* __restrict__ w3_ws,
    const float* __restrict__ w3_wsb, const float* __restrict__ w3_wv,
    const float* __restrict__ w3_wsv, const float* __restrict__ w3_wsvb,
    float* __restrict__ out, int N, int E)
{
    extern __shared__ float sm[];
    const int tid = threadIdx.x;

    // ---------- phase A: stage weights in smem ----------
    smcopy_pad(sm + O_WES, w1_ws + 128 * 64, 32);
    smcopy_pad(sm + O_WVN, w1_ws + 288 * 64, 33);
    for (int i = tid; i < 72; i += BLK) sm[O_WVN + 33 * 72 + i] = 0.f;
    smcopy(sm + O_B1,   w1_wsb, 64);
    smcopy(sm + O_WHE,  w1_wh + 16 * 33, 33);
    for (int i = tid + 33; i < 36; i += BLK) sm[O_WHE + i] = 0.f;
    smcopy(sm + O_WV1,  w1_wv, 132);
    for (int i = tid + 132; i < 136; i += BLK) sm[O_WV1 + i] = 0.f;
    smcopy(sm + O_WSV1, w1_wsv, 256);
    smcopy(sm + O_BSV1, w1_wsvb, 4);
    smcopy(sm + O_W2H,  w2_wh, 16);
    smcopy_pad(sm + O_W2S, w2_ws, 68);
    smcopy(sm + O_B2,   w2_wsb, 64);
    smcopy(sm + O_WV2,  w2_wv, 16);
    smcopy(sm + O_WSV2, w2_wsv, 256);
    smcopy(sm + O_BSV2, w2_wsvb, 4);
    smcopy(sm + O_W3H,  w3_wh, 16);
    smcopy_pad(sm + O_W3S, w3_ws, 68);
    smcopy(sm + O_B3,   w3_wsb, 64);
    smcopy(sm + O_WV3,  w3_wv, 16);
    smcopy(sm + O_WSV3, w3_wsv, 256);
    smcopy(sm + O_BSV3, w3_wsvb, 4);
    __syncthreads();

    // ---------- phase B: per-node prep (weights L1-resident per SM) ----------
    {
        const int chunk = (N + gridDim.x - 1) / gridDim.x;
        const int n0 = blockIdx.x * chunk;
        const int n1 = min(N, n0 + chunk);
        for (int idx = n0 * 64 + tid; idx < n1 * 64; idx += BLK) g_s_acc[idx] = 0.f;
        for (int idx = n0 * 12 + tid; idx < n1 * 12; idx += BLK) g_v_acc[idx] = 0.f;
        for (int idx = n0 + tid; idx < n1; idx += BLK) g_cnt[idx] = 0.f;

        const int g  = tid >> 7;         // group 0..2 (128 threads each)
        const int lt = tid & 127;
        float* xs = sm + O_XS + g * 128;
        const int iters = (chunk + 2) / 3;
        for (int i = 0; i < iters; i++) {
            int n = n0 + i * 3 + g;
            bool act = n < n1;
            if (act) xs[lt] = node_s[n * 128 + lt];
            asm volatile("bar.sync %0, 128;" :: "r"(g + 1) : "memory");
            if (act) {
                if (lt < 66) {
                    int h = (lt < 33) ? lt : lt - 33;
                    bool is_src = (lt < 33);
                    int base = is_src ? 0 : 17;
                    const float* v = node_v + n * 48;
                    float x = 0.f, y = 0.f, z = 0.f;
#pragma unroll
                    for (int k = 0; k < 16; k++) {
                        float w = w1_wh[(base + k) * 33 + h];
                        x += v[k*3+0] * w; y += v[k*3+1] * w; z += v[k*3+2] * w;
                    }
                    float4 o = make_float4(x, y, z, 0.f);
                    if (is_src) g_ah_src[n * 34 + h] = o;
                    else        g_ah_dst[n * 34 + h] = o;
                } else if (lt == 66) {
                    g_ah_src[n * 34 + 33] = make_float4(0.f, 0.f, 0.f, 0.f);
                } else if (lt == 67) {
                    g_ah_dst[n * 34 + 33] = make_float4(0.f, 0.f, 0.f, 0.f);
                }
                int j = lt & 63;
                const float* W = w1_ws + ((lt >= 64) ? 160 * 64 : 0) + j;
                float acc = 0.f;
#pragma unroll 16
                for (int k = 0; k < 128; k++) acc += xs[k] * W[k * 64];
                if (lt < 64) g_as_src[n * 64 + j] = acc;
                else         g_as_dst[n * 64 + j] = acc;
            }
            asm volatile("bar.sync %0, 128;" :: "r"(g + 1) : "memory");
        }
    }
    grid_barrier(0, gridDim.x);

    // ---------- phase C: edges (lane pair per edge) ----------
    {
        const int p = tid & 1;
        const int half = 36 * p;
        const int hs = 17 * p;
        const int pps = gridDim.x * (BLK >> 1);
        const int base = blockIdx.x * (BLK >> 1) + (tid >> 1);
        const int iters = (E + pps - 1) / pps;

        for (int it = 0; it < iters; it++) {
            int P = base + it * pps;
            bool valid = P < E;
            int e = valid ? P : 0;
            int src = ei[e];
            int dst = ei[e + E];
            float ev0 = edge_v[e*3+0], ev1 = edge_v[e*3+1], ev2 = edge_v[e*3+2];

            ull acc[16];
            {
                const float4* As = (const float4*)(g_as_src + src * 64 + 32 * p);
                const float4* Bs = (const float4*)(g_as_dst + dst * 64 + 32 * p);
                const float4* Cb = (const float4*)(sm + O_B1 + 32 * p);
#pragma unroll
                for (int j = 0; j < 8; j++) {
                    float4 a = As[j], b = Bs[j], c = Cb[j];
                    acc[2*j]   = pack2(a.x + b.x + c.x, a.y + b.y + c.y);
                    acc[2*j+1] = pack2(a.z + b.z + c.z, a.w + b.w + c.w);
                }
            }
            {
                const float4* ES = (const float4*)(edge_s + (size_t)e * 32);
#pragma unroll
                for (int k4 = 0; k4 < 8; k4++) {
                    float4 es = ES[k4];
                    fma_row32(acc, es.x, sm + O_WES + (k4*4+0) * 72 + half);
                    fma_row32(acc, es.y, sm + O_WES + (k4*4+1) * 72 + half);
                    fma_row32(acc, es.z, sm + O_WES + (k4*4+2) * 72 + half);
                    fma_row32(acc, es.w, sm + O_WES + (k4*4+3) * 72 + half);
                }
            }
            float vn_own[17];
            float vo1p[12];
#pragma unroll
            for (int i = 0; i < 12; i++) vo1p[i] = 0.f;
            {
                const float4* A = g_ah_src + src * 34 + hs;
                const float4* B = g_ah_dst + dst * 34 + hs;
#pragma unroll
                for (int k = 0; k < 17; k++) {
                    int h = hs + k;
                    float4 a = A[k];
                    float4 b = B[k];
                    float w = sm[O_WHE + h];
                    float x = a.x + b.x + ev0 * w;
                    float y = a.y + b.y + ev1 * w;
                    float z = a.z + b.z + ev2 * w;
                    float vn = fsqrt_(fmaxf(x*x + y*y + z*z, 1e-8f));
                    vn_own[k] = vn;
                    fma_row32(acc, vn, sm + O_WVN + h * 72 + half);
                    float4 wv = *(const float4*)(sm + O_WV1 + h * 4);
                    vo1p[0] += wv.x * x; vo1p[1]  += wv.x * y; vo1p[2]  += wv.x * z;
                    vo1p[3] += wv.y * x; vo1p[4]  += wv.y * y; vo1p[5]  += wv.y * z;
                    vo1p[6] += wv.z * x; vo1p[7]  += wv.z * y; vo1p[8]  += wv.z * z;
                    vo1p[9] += wv.w * x; vo1p[10] += wv.w * y; vo1p[11] += wv.w * z;
                }
#pragma unroll
                for (int k = 0; k < 17; k++) {
                    float vnp = __shfl_xor_sync(0xffffffffu, vn_own[k], 1);
                    int h = p ? k : 17 + k;
                    fma_row32(acc, vnp, sm + O_WVN + h * 72 + half);
                }
            }
            float vo1[12];
#pragma unroll
            for (int i = 0; i < 12; i++)
                vo1[i] = vo1p[i] + __shfl_xor_sync(0xffffffffu, vo1p[i], 1);

            float s1f[32];
#pragma unroll
            for (int j = 0; j < 16; j++) unpack2(s1f[2*j], s1f[2*j+1], acc[j]);

            float v1[12];
            {
                float p0 = 0.f, p1 = 0.f, p2 = 0.f, p3 = 0.f;
#pragma unroll
                for (int r = 0; r < 32; r++) {
                    float t = fsig(s1f[r]);
                    float4 w = *(const float4*)(sm + O_WSV1 + (32 * p + r) * 4);
                    p0 += t * w.x; p1 += t * w.y; p2 += t * w.z; p3 += t * w.w;
                }
                float g0 = sm[O_BSV1+0] + p0 + __shfl_xor_sync(0xffffffffu, p0, 1);
                float g1 = sm[O_BSV1+1] + p1 + __shfl_xor_sync(0xffffffffu, p1, 1);
                float g2 = sm[O_BSV1+2] + p2 + __shfl_xor_sync(0xffffffffu, p2, 1);
                float g3 = sm[O_BSV1+3] + p3 + __shfl_xor_sync(0xffffffffu, p3, 1);
                g0 = fsig(g0); g1 = fsig(g1); g2 = fsig(g2); g3 = fsig(g3);
#pragma unroll
                for (int c = 0; c < 3; c++) {
                    v1[0*3+c] = vo1[0*3+c] * g0;
                    v1[1*3+c] = vo1[1*3+c] * g1;
                    v1[2*3+c] = vo1[2*3+c] * g2;
                    v1[3*3+c] = vo1[3*3+c] * g3;
                }
#pragma unroll
                for (int r = 0; r < 32; r++) s1f[r] = fmaxf(s1f[r], 0.f);
            }

            float s2f[32], v2[12];
            gvp64(p, sm, s1f, v1, s2f, v2, O_W2H, O_W2S, O_B2, O_WV2, O_WSV2, O_BSV2, false);
            float s3f[32], v3[12];
            gvp64(p, sm, s2f, v2, s3f, v3, O_W3H, O_W3S, O_B3, O_WV3, O_WSV3, O_BSV3, true);

            if (valid) {
                float* sa = g_s_acc + (size_t)dst * 64 + 32 * p;
#pragma unroll
                for (int j = 0; j < 8; j++) {
                    asm volatile("red.global.add.v4.f32 [%0], {%1, %2, %3, %4};"
                        :: "l"(sa + 4*j),
                           "f"(s3f[4*j]), "f"(s3f[4*j+1]), "f"(s3f[4*j+2]), "f"(s3f[4*j+3])
                        : "memory");
                }
                float* va = g_v_acc + (size_t)dst * 12 + 6 * p;
#pragma unroll
                for (int j = 0; j < 3; j++) {
                    asm volatile("red.global.add.v2.f32 [%0], {%1, %2};"
                        :: "l"(va + 2*j), "f"(v3[6*p + 2*j]), "f"(v3[6*p + 2*j+1])
                        : "memory");
                }
                if (p == 0) atomicAdd(g_cnt + dst, 1.0f);
            }
        }
    }
    grid_barrier(1, gridDim.x);

    // ---------- phase D: finalize ----------
    {
        const int total = N * 64 + N * 4;
        const int stride = gridDim.x * BLK;
        for (int idx = blockIdx.x * BLK + tid; idx < total; idx += stride) {
            if (idx < N * 64) {
                int n = idx >> 6;
                int j = idx & 63;
                float denom = fmaxf(g_cnt[n], 1.0f);
                float s = g_s_acc[idx] / denom;
                float m = (mask[n] != 0) ? 1.0f : 0.0f;
                float val;
                if (j < 7)       val = cosf(s);
                else if (j < 14) val = sinf(s);
                else             val = expf(s);
                out[idx] = val * m;
            } else {
                int k = idx - N * 64;
                int n = k >> 2;
                int o = k & 3;
                float denom = fmaxf(g_cnt[n], 1.0f);
                float x = g_v_acc[n*12 + o*3 + 0] / denom;
                float y = g_v_acc[n*12 + o*3 + 1] / denom;
                float z = g_v_acc[n*12 + o*3 + 2] / denom;
                float mag = sqrtf(x*x + y*y + z*z);
                float m = (mask[n] != 0) ? 1.0f : 0.0f;
                float sc = m / (mag + 1e-8f);
                float* vout = out + N * 64 + n * 12 + o * 3;
                vout[0] = x * sc; vout[1] = y * sc; vout[2] = z * sc;
            }
        }
    }
}

extern "C" void kernel_launch(void* const* d_in, const int* in_sizes, int n_in,
                              void* d_out, int out_size)
{
    const float* node_s = (const float*)d_in[0];
    const float* node_v = (const float*)d_in[1];
    const int*   ei     = (const int*)d_in[2];
    const float* edge_s = (const float*)d_in[3];
    const float* edge_v = (const float*)d_in[4];
    const int*   mask   = (const int*)d_in[5];

    int N = in_sizes[0] / 128;
    int E = in_sizes[3] / 32;
    float* out = (float*)d_out;

    cudaFuncSetAttribute(mega_kernel,
                         cudaFuncAttributeMaxDynamicSharedMemorySize, SMEM_BYTES);
    mega_kernel<<<GRID, BLK, SMEM_BYTES>>>(
        node_s, node_v, ei, edge_s, edge_v, mask,
        (const float*)d_in[6],  (const float*)d_in[7],  (const float*)d_in[8],
        (const float*)d_in[9],  (const float*)d_in[10], (const float*)d_in[11],
        (const float*)d_in[12], (const float*)d_in[13], (const float*)d_in[14],
        (const float*)d_in[15], (const float*)d_in[16], (const float*)d_in[17],
        (const float*)d_in[18], (const float*)d_in[19], (const float*)d_in[20],
        (const float*)d_in[21], (const float*)d_in[22], (const float*)d_in[23],
        out, N, E);
}